// round 2
// baseline (speedup 1.0000x reference)
#include <cuda_runtime.h>
#include <cstdint>

#define SEQ 1024
#define DIMC 1024
#define NHEADS 16
#define HDIM 64
#define NBATCH 2
#define NBH (NBATCH*NHEADS)   // 32

// ---------------- scratch (device globals; no runtime allocation) -------------
__device__ float g_qkv[3][NBH][SEQ][HDIM];   // 24 MB   q/k/v in [bh][s][d]
__device__ float g_kern[NBH][SEQ][SEQ];      // 134 MB  unnormalized kernel
__device__ float g_rowsum[NBH][SEQ];         // 128 KB
__device__ float g_y[NBATCH*SEQ][DIMC];      // 8 MB    pre-projection activations

// ---------------- packed f32x2 helpers ----------------------------------------
__device__ __forceinline__ unsigned long long f2add(unsigned long long a,
                                                    unsigned long long b) {
    unsigned long long d;
    asm("add.rn.f32x2 %0, %1, %2;" : "=l"(d) : "l"(a), "l"(b));
    return d;
}
__device__ __forceinline__ unsigned long long pk2(float x, float y) {
    return (unsigned long long)__float_as_uint(x) |
           ((unsigned long long)__float_as_uint(y) << 32);
}

// ==============================================================================
// SGEMM (NT): C[m,n] = sum_k A[m,k]*B[n,k] + bias[n]
// BM=BN=128, BK=8, 256 threads, 8x8 microtile.
// MODE 0: A = g_y (device global), store C row-major (the output projection)
// MODE 1: A = x, scatter results into g_qkv with (t,h,d) decode (the qkv proj)
// ==============================================================================
template<int MODE>
__global__ __launch_bounds__(256) void sgemm_nt(
    const float* __restrict__ A, const float* __restrict__ B,
    const float* __restrict__ bias, float* __restrict__ C,
    int M, int N, int K)
{
    __shared__ float As[8][132];
    __shared__ float Bs[8][132];

    const int tid = threadIdx.x;
    const int tx  = tid & 15;
    const int ty  = tid >> 4;
    const int mb  = blockIdx.y * 128;
    const int nb  = blockIdx.x * 128;

    const float* Ap = (MODE == 0) ? &g_y[0][0] : A;

    float acc[8][8];
#pragma unroll
    for (int i = 0; i < 8; i++)
#pragma unroll
        for (int j = 0; j < 8; j++) acc[i][j] = 0.f;

    const int lr = tid >> 1;          // 0..127 (row of A-tile / row of B-tile)
    const int lk = (tid & 1) * 4;     // 0 or 4
    const float* aptr = Ap + (size_t)(mb + lr) * K + lk;
    const float* bptr = B  + (size_t)(nb + lr) * K + lk;

    for (int k0 = 0; k0 < K; k0 += 8) {
        float4 av = *(const float4*)(aptr + k0);
        float4 bv = *(const float4*)(bptr + k0);
        As[lk+0][lr] = av.x; As[lk+1][lr] = av.y;
        As[lk+2][lr] = av.z; As[lk+3][lr] = av.w;
        Bs[lk+0][lr] = bv.x; Bs[lk+1][lr] = bv.y;
        Bs[lk+2][lr] = bv.z; Bs[lk+3][lr] = bv.w;
        __syncthreads();
#pragma unroll
        for (int kk = 0; kk < 8; kk++) {
            float a[8], b[8];
            *(float4*)&a[0] = *(const float4*)&As[kk][ty*8];
            *(float4*)&a[4] = *(const float4*)&As[kk][ty*8+4];
            *(float4*)&b[0] = *(const float4*)&Bs[kk][tx*8];
            *(float4*)&b[4] = *(const float4*)&Bs[kk][tx*8+4];
#pragma unroll
            for (int i = 0; i < 8; i++)
#pragma unroll
                for (int j = 0; j < 8; j++)
                    acc[i][j] += a[i] * b[j];
        }
        __syncthreads();
    }

    if (MODE == 1) {
        // scatter: col n -> (t, h, d); row m -> (b, s); write g_qkv[t][b*16+h][s][d]
#pragma unroll
        for (int i = 0; i < 8; i++) {
            int m = mb + ty*8 + i;
            int bb = m >> 10, s = m & 1023;
#pragma unroll
            for (int j = 0; j < 8; j++) {
                int n = nb + tx*8 + j;
                float v = acc[i][j] + bias[n];
                int tsel = n >> 10;
                int rem  = n & 1023;
                int h    = rem >> 6;
                int d    = rem & 63;
                g_qkv[tsel][bb*NHEADS + h][s][d] = v;
            }
        }
    } else {
#pragma unroll
        for (int i = 0; i < 8; i++) {
            int m = mb + ty*8 + i;
            float* crow = C + (size_t)m * N + nb + tx*8;
#pragma unroll
            for (int j = 0; j < 8; j++)
                crow[j] = acc[i][j] + bias[nb + tx*8 + j];
        }
    }
}

// ==============================================================================
// Laplacian kernel: kern[bh,i,j] = exp(-|q_i - k_j|_1 / 16), plus row sums.
// Grid (16 i-tiles, 32 bh). CTA = 64 i x 1024 j sweep. 256 threads, 4x4 microtile.
// Packed f32x2: diff = q + (-k) [FMA pipe], abs via 64-bit AND [ALU pipe],
// accumulate with f32x2 add [FMA pipe].
// ==============================================================================
__global__ __launch_bounds__(256) void laplace_kern()
{
    __shared__ unsigned long long qs[32][64];   // [d/2][i]
    __shared__ unsigned long long ks[32][64];   // [d/2][j]  (stores -k)

    const int tid = threadIdx.x;
    const int tx  = tid & 15;
    const int ty  = tid >> 4;
    const int it  = blockIdx.x;     // 0..15
    const int bh  = blockIdx.y;     // 0..31

    const float* Q  = &g_qkv[0][bh][it*64][0];
    const float* Kp = &g_qkv[1][bh][0][0];

#pragma unroll
    for (int r = 0; r < 4; r++) {
        int idx = r*1024 + tid*4;
        int i = idx >> 6, d = idx & 63;
        float4 v = *(const float4*)(Q + i*64 + d);
        qs[(d>>1)    ][i] = pk2(v.x, v.y);
        qs[(d>>1) + 1][i] = pk2(v.z, v.w);
    }

    float rs[4] = {0.f, 0.f, 0.f, 0.f};
    float* kout = &g_kern[bh][it*64][0];

    for (int jt = 0; jt < 16; jt++) {
#pragma unroll
        for (int r = 0; r < 4; r++) {
            int idx = r*1024 + tid*4;
            int j = idx >> 6, d = idx & 63;
            float4 v = *(const float4*)(Kp + (jt*64 + j)*64 + d);
            ks[(d>>1)    ][j] = pk2(-v.x, -v.y);
            ks[(d>>1) + 1][j] = pk2(-v.z, -v.w);
        }
        __syncthreads();

        unsigned long long a2[4][4];
#pragma unroll
        for (int ii = 0; ii < 4; ii++)
#pragma unroll
            for (int jj = 0; jj < 4; jj++) a2[ii][jj] = 0ull;

#pragma unroll
        for (int d2 = 0; d2 < 32; d2++) {
            ulonglong2 qa = *(const ulonglong2*)&qs[d2][ty*4];
            ulonglong2 qb = *(const ulonglong2*)&qs[d2][ty*4 + 2];
            ulonglong2 ka = *(const ulonglong2*)&ks[d2][tx*4];
            ulonglong2 kb = *(const ulonglong2*)&ks[d2][tx*4 + 2];
            unsigned long long q2[4] = {qa.x, qa.y, qb.x, qb.y};
            unsigned long long k2[4] = {ka.x, ka.y, kb.x, kb.y};
#pragma unroll
            for (int ii = 0; ii < 4; ii++)
#pragma unroll
                for (int jj = 0; jj < 4; jj++) {
                    unsigned long long t = f2add(q2[ii], k2[jj])
                                         & 0x7FFFFFFF7FFFFFFFull;
                    a2[ii][jj] = f2add(a2[ii][jj], t);
                }
        }

#pragma unroll
        for (int ii = 0; ii < 4; ii++) {
            float4 o;
            float* op = &o.x;
#pragma unroll
            for (int jj = 0; jj < 4; jj++) {
                unsigned long long v = a2[ii][jj];
                float dist = __uint_as_float((unsigned)v)
                           + __uint_as_float((unsigned)(v >> 32));
                float kv = __expf(-0.0625f * dist);   // exp(-4*dist/64)
                op[jj] = kv;
                rs[ii] += kv;
            }
            *(float4*)(kout + (size_t)(ty*4 + ii)*1024 + jt*64 + tx*4) = o;
        }
        __syncthreads();
    }

    // row-sum reduce across the 16 tx lanes (lanes 0-15 / 16-31 of each warp)
#pragma unroll
    for (int ii = 0; ii < 4; ii++) {
        float v = rs[ii];
        v += __shfl_xor_sync(0xffffffffu, v, 1);
        v += __shfl_xor_sync(0xffffffffu, v, 2);
        v += __shfl_xor_sync(0xffffffffu, v, 4);
        v += __shfl_xor_sync(0xffffffffu, v, 8);
        if (tx == 0) g_rowsum[bh][it*64 + ty*4 + ii] = v;
    }
}

// ==============================================================================
// attn@v + row normalize + depthwise conv local branch -> g_y[b*S+s][h*64+d]
// Per (bh, 64-row i-tile): GEMM 64x64x1024, j-step 32. 256 threads, 4x4 microtile.
// ==============================================================================
__global__ __launch_bounds__(256) void attnv_kern(const float* __restrict__ dwc_w,
                                                  const float* __restrict__ dwc_b)
{
    __shared__ float kt[32][68];   // [j][i] transposed kern tile (pad 68: aligned rows)
    __shared__ float vs[32][64];   // [j][d]

    const int tid = threadIdx.x;
    const int tx  = tid & 15;
    const int ty  = tid >> 4;
    const int it  = blockIdx.x;
    const int bh  = blockIdx.y;
    const int bb  = bh >> 4;
    const int h   = bh & 15;

    const float* Kr = &g_kern[bh][it*64][0];
    const float* V  = &g_qkv[2][bh][0][0];

    float acc[4][4];
#pragma unroll
    for (int i = 0; i < 4; i++)
#pragma unroll
        for (int j = 0; j < 4; j++) acc[i][j] = 0.f;

    for (int jt = 0; jt < 32; jt++) {
#pragma unroll
        for (int r = 0; r < 2; r++) {
            int idx = r*1024 + tid*4;
            // kern tile 64i x 32j, store transposed
            int i  = idx >> 5, jc = idx & 31;
            float4 kv4 = *(const float4*)(Kr + (size_t)i*1024 + jt*32 + jc);
            kt[jc+0][i] = kv4.x; kt[jc+1][i] = kv4.y;
            kt[jc+2][i] = kv4.z; kt[jc+3][i] = kv4.w;
            // V tile 32j x 64d, natural
            int j = idx >> 6, d = idx & 63;
            float4 vv = *(const float4*)(V + (jt*32 + j)*64 + d);
            *(float4*)&vs[j][d] = vv;
        }
        __syncthreads();
#pragma unroll
        for (int kk = 0; kk < 32; kk++) {
            float4 av = *(const float4*)&kt[kk][ty*4];
            float4 bv = *(const float4*)&vs[kk][tx*4];
            const float* ap = &av.x;
            const float* bp = &bv.x;
#pragma unroll
            for (int ii = 0; ii < 4; ii++)
#pragma unroll
                for (int dd = 0; dd < 4; dd++)
                    acc[ii][dd] += ap[ii] * bp[dd];
        }
        __syncthreads();
    }

    const int d0 = tx*4;
#pragma unroll
    for (int ii = 0; ii < 4; ii++) {
        int s = it*64 + ty*4 + ii;
        float scale = 1.0f / (g_rowsum[bh][s] + 1e-6f);
        float4 v0 = *(const float4*)(V + s*64 + d0);
        float4 vm = (s > 0)        ? *(const float4*)(V + (s-1)*64 + d0)
                                   : make_float4(0.f,0.f,0.f,0.f);
        float4 vp = (s < SEQ - 1)  ? *(const float4*)(V + (s+1)*64 + d0)
                                   : make_float4(0.f,0.f,0.f,0.f);
        const float* vmp = &vm.x;
        const float* v0p = &v0.x;
        const float* vpp = &vp.x;
#pragma unroll
        for (int dd = 0; dd < 4; dd++) {
            int c = h*64 + d0 + dd;
            float w0 = dwc_w[c*3+0], w1 = dwc_w[c*3+1], w2 = dwc_w[c*3+2];
            float loc = w0*vmp[dd] + w1*v0p[dd] + w2*vpp[dd] + dwc_b[c];
            g_y[bb*SEQ + s][c] = acc[ii][dd]*scale + loc;
        }
    }
}

// ==============================================================================
extern "C" void kernel_launch(void* const* d_in, const int* in_sizes, int n_in,
                              void* d_out, int out_size)
{
    const float* x      = (const float*)d_in[0];
    const float* qkv_w  = (const float*)d_in[1];
    const float* qkv_b  = (const float*)d_in[2];
    const float* proj_w = (const float*)d_in[3];
    const float* proj_b = (const float*)d_in[4];
    const float* dwc_w  = (const float*)d_in[5];
    const float* dwc_b  = (const float*)d_in[6];
    float* out = (float*)d_out;

    // 1) qkv projection: [2048,3072] = x[2048,1024] @ qkv_w^T, scatter to q/k/v
    sgemm_nt<1><<<dim3(24, 16), 256>>>(x, qkv_w, qkv_b, nullptr, 2048, 3072, 1024);
    // 2) Laplacian L1 kernel matrix + row sums
    laplace_kern<<<dim3(16, 32), 256>>>();
    // 3) kern @ v, normalize, + depthwise conv local branch -> g_y
    attnv_kern<<<dim3(16, 32), 256>>>(dwc_w, dwc_b);
    // 4) output projection -> d_out
    sgemm_nt<0><<<dim3(8, 16), 256>>>(nullptr, proj_w, proj_b, out, 2048, 1024, 1024);
}

// round 3
// speedup vs baseline: 1.6474x; 1.6474x over previous
#include <cuda_runtime.h>
#include <cstdint>

#define SEQ 1024
#define DIMC 1024
#define NHEADS 16
#define HDIM 64
#define NBATCH 2
#define NBH (NBATCH*NHEADS)   // 32

// ---------------- scratch (device globals; no runtime allocation) -------------
__device__ float g_qkv[3][NBH][SEQ][HDIM];   // 24 MB   q/k/v in [bh][s][d]
__device__ float g_kern[NBH][SEQ][SEQ];      // 134 MB  unnormalized kernel
__device__ float g_rowsum[NBH][SEQ];         // 128 KB
__device__ float g_y[NBATCH*SEQ][DIMC];      // 8 MB    pre-projection activations

// ---------------- small helpers -----------------------------------------------
__device__ __forceinline__ unsigned long long f2add(unsigned long long a,
                                                    unsigned long long b) {
    unsigned long long d;
    asm("add.rn.f32x2 %0, %1, %2;" : "=l"(d) : "l"(a), "l"(b));
    return d;
}
__device__ __forceinline__ unsigned long long pk2(float x, float y) {
    return (unsigned long long)__float_as_uint(x) |
           ((unsigned long long)__float_as_uint(y) << 32);
}
__device__ __forceinline__ uint32_t smem_u32(const void* p) {
    return (uint32_t)__cvta_generic_to_shared(p);
}
__device__ __forceinline__ void cp16(uint32_t s, const void* g) {
    asm volatile("cp.async.cg.shared.global [%0], [%1], 16;\n" :: "r"(s), "l"(g));
}
__device__ __forceinline__ uint32_t f2tf32(float f) {
    uint32_t r; asm("cvt.rna.tf32.f32 %0, %1;" : "=r"(r) : "f"(f)); return r;
}
__device__ __forceinline__ void mma_tf32(float c[4],
        uint32_t a0, uint32_t a1, uint32_t a2, uint32_t a3,
        uint32_t b0, uint32_t b1) {
    asm volatile(
        "mma.sync.aligned.m16n8k8.row.col.f32.tf32.tf32.f32 "
        "{%0,%1,%2,%3}, {%4,%5,%6,%7}, {%8,%9}, {%0,%1,%2,%3};"
        : "+f"(c[0]), "+f"(c[1]), "+f"(c[2]), "+f"(c[3])
        : "r"(a0), "r"(a1), "r"(a2), "r"(a3), "r"(b0), "r"(b1));
}

// ==============================================================================
// Tensor-core tf32 GEMM (NT): C[m,n] = sum_k A[m,k]*B[n,k] + bias[n]
// BM=BN=128, BK=16, 256 threads (8 warps, each 32x64), cp.async double-buffer.
// MODE 0: A = g_y, plain row-major store (output projection)
// MODE 1: A = x, scatter into g_qkv with (t,h,d) decode (qkv projection)
// ==============================================================================
template<int MODE>
__global__ __launch_bounds__(256) void mma_nt(
    const float* __restrict__ A, const float* __restrict__ B,
    const float* __restrict__ bias, float* __restrict__ C,
    int M, int N, int K)
{
    constexpr int BK  = 16;
    constexpr int PAD = 20;                 // floats per smem row (80B: 16B-aligned)
    __shared__ float As[2][128][PAD];
    __shared__ float Bs[2][128][PAD];

    const int tid  = threadIdx.x;
    const int warp = tid >> 5;
    const int lane = tid & 31;
    const int gr   = lane >> 2;             // groupID
    const int tg   = lane & 3;              // thread-in-group
    const int wm   = (warp & 3) * 32;       // warp row offset (4 warps in M)
    const int wn   = (warp >> 2) * 64;      // warp col offset (2 warps in N)
    const int mb   = blockIdx.y * 128;
    const int nb   = blockIdx.x * 128;

    const float* Ap = (MODE == 0) ? &g_y[0][0] : A;

    // global load coordinates: 2 float4 per thread per matrix per tile
    const int lrow = tid >> 2;              // 0..63 (and +64)
    const int lcol = (tid & 3) * 4;         // 0,4,8,12
    const float* aG = Ap + (size_t)(mb + lrow) * K + lcol;
    const float* bG = B  + (size_t)(nb + lrow) * K + lcol;

    float acc[2][8][4];
#pragma unroll
    for (int i = 0; i < 2; i++)
#pragma unroll
        for (int j = 0; j < 8; j++)
#pragma unroll
            for (int r = 0; r < 4; r++) acc[i][j][r] = 0.f;

    auto load_tiles = [&](int buf, int k0) {
        cp16(smem_u32(&As[buf][lrow     ][lcol]), aG + k0);
        cp16(smem_u32(&As[buf][lrow + 64][lcol]), aG + (size_t)64 * K + k0);
        cp16(smem_u32(&Bs[buf][lrow     ][lcol]), bG + k0);
        cp16(smem_u32(&Bs[buf][lrow + 64][lcol]), bG + (size_t)64 * K + k0);
        asm volatile("cp.async.commit_group;\n");
    };

    const int nK = K / BK;
    load_tiles(0, 0);

    for (int kt = 0; kt < nK; kt++) {
        asm volatile("cp.async.wait_group 0;\n");
        __syncthreads();
        if (kt + 1 < nK) load_tiles((kt + 1) & 1, (kt + 1) * BK);
        const int buf = kt & 1;

#pragma unroll
        for (int ks = 0; ks < 2; ks++) {
            const int k0 = ks * 8;
            uint32_t af[2][4];
#pragma unroll
            for (int i = 0; i < 2; i++) {
                const int r = wm + i * 16;
                af[i][0] = f2tf32(As[buf][r + gr    ][k0 + tg    ]);
                af[i][1] = f2tf32(As[buf][r + gr + 8][k0 + tg    ]);
                af[i][2] = f2tf32(As[buf][r + gr    ][k0 + tg + 4]);
                af[i][3] = f2tf32(As[buf][r + gr + 8][k0 + tg + 4]);
            }
#pragma unroll
            for (int j = 0; j < 8; j++) {
                const int n = wn + j * 8;
                uint32_t b0 = f2tf32(Bs[buf][n + gr][k0 + tg    ]);
                uint32_t b1 = f2tf32(Bs[buf][n + gr][k0 + tg + 4]);
#pragma unroll
                for (int i = 0; i < 2; i++)
                    mma_tf32(acc[i][j], af[i][0], af[i][1], af[i][2], af[i][3],
                             b0, b1);
            }
        }
    }

    // epilogue
#pragma unroll
    for (int i = 0; i < 2; i++) {
#pragma unroll
        for (int j = 0; j < 8; j++) {
            const int r0 = mb + wm + i * 16 + gr;
            const int c0 = nb + wn + j * 8 + 2 * tg;
            const float bia0 = bias[c0], bia1 = bias[c0 + 1];
            if (MODE == 1) {
#pragma unroll
                for (int e = 0; e < 4; e++) {
                    const int m = r0 + (e >> 1) * 8;
                    const int n = c0 + (e & 1);
                    const float v = acc[i][j][e] + ((e & 1) ? bia1 : bia0);
                    const int tsel = n >> 10, rem = n & 1023;
                    const int h = rem >> 6, d = rem & 63;
                    const int bb = m >> 10, s = m & 1023;
                    g_qkv[tsel][bb * NHEADS + h][s][d] = v;
                }
            } else {
                float2 lo = make_float2(acc[i][j][0] + bia0, acc[i][j][1] + bia1);
                float2 hi = make_float2(acc[i][j][2] + bia0, acc[i][j][3] + bia1);
                *(float2*)&C[(size_t)r0 * N + c0]        = lo;
                *(float2*)&C[(size_t)(r0 + 8) * N + c0]  = hi;
            }
        }
    }
}

// ==============================================================================
// Laplacian kernel: kern[bh,i,j] = exp(-|q_i - k_j|_1 / 16), plus row sums.
// Grid (16 i-tiles, 32 bh). CTA = 64 i x 1024 j sweep. 256 threads, 4x4 microtile.
// ==============================================================================
__global__ __launch_bounds__(256) void laplace_kern()
{
    __shared__ unsigned long long qs[32][64];   // [d/2][i]
    __shared__ unsigned long long ks[32][64];   // [d/2][j]  (stores -k)

    const int tid = threadIdx.x;
    const int tx  = tid & 15;
    const int ty  = tid >> 4;
    const int it  = blockIdx.x;     // 0..15
    const int bh  = blockIdx.y;     // 0..31

    const float* Q  = &g_qkv[0][bh][it*64][0];
    const float* Kp = &g_qkv[1][bh][0][0];

#pragma unroll
    for (int r = 0; r < 4; r++) {
        int idx = r*1024 + tid*4;
        int i = idx >> 6, d = idx & 63;
        float4 v = *(const float4*)(Q + i*64 + d);
        qs[(d>>1)    ][i] = pk2(v.x, v.y);
        qs[(d>>1) + 1][i] = pk2(v.z, v.w);
    }

    float rs[4] = {0.f, 0.f, 0.f, 0.f};
    float* kout = &g_kern[bh][it*64][0];

    for (int jt = 0; jt < 16; jt++) {
#pragma unroll
        for (int r = 0; r < 4; r++) {
            int idx = r*1024 + tid*4;
            int j = idx >> 6, d = idx & 63;
            float4 v = *(const float4*)(Kp + (jt*64 + j)*64 + d);
            ks[(d>>1)    ][j] = pk2(-v.x, -v.y);
            ks[(d>>1) + 1][j] = pk2(-v.z, -v.w);
        }
        __syncthreads();

        unsigned long long a2[4][4];
#pragma unroll
        for (int ii = 0; ii < 4; ii++)
#pragma unroll
            for (int jj = 0; jj < 4; jj++) a2[ii][jj] = 0ull;

#pragma unroll
        for (int d2 = 0; d2 < 32; d2++) {
            ulonglong2 qa = *(const ulonglong2*)&qs[d2][ty*4];
            ulonglong2 qb = *(const ulonglong2*)&qs[d2][ty*4 + 2];
            ulonglong2 ka = *(const ulonglong2*)&ks[d2][tx*4];
            ulonglong2 kb = *(const ulonglong2*)&ks[d2][tx*4 + 2];
            unsigned long long q2[4] = {qa.x, qa.y, qb.x, qb.y};
            unsigned long long k2[4] = {ka.x, ka.y, kb.x, kb.y};
#pragma unroll
            for (int ii = 0; ii < 4; ii++)
#pragma unroll
                for (int jj = 0; jj < 4; jj++) {
                    unsigned long long t = f2add(q2[ii], k2[jj])
                                         & 0x7FFFFFFF7FFFFFFFull;
                    a2[ii][jj] = f2add(a2[ii][jj], t);
                }
        }

#pragma unroll
        for (int ii = 0; ii < 4; ii++) {
            float4 o;
            float* op = &o.x;
#pragma unroll
            for (int jj = 0; jj < 4; jj++) {
                unsigned long long v = a2[ii][jj];
                float dist = __uint_as_float((unsigned)v)
                           + __uint_as_float((unsigned)(v >> 32));
                float kv = __expf(-0.0625f * dist);   // exp(-4*dist/64)
                op[jj] = kv;
                rs[ii] += kv;
            }
            *(float4*)(kout + (size_t)(ty*4 + ii)*1024 + jt*64 + tx*4) = o;
        }
        __syncthreads();
    }

#pragma unroll
    for (int ii = 0; ii < 4; ii++) {
        float v = rs[ii];
        v += __shfl_xor_sync(0xffffffffu, v, 1);
        v += __shfl_xor_sync(0xffffffffu, v, 2);
        v += __shfl_xor_sync(0xffffffffu, v, 4);
        v += __shfl_xor_sync(0xffffffffu, v, 8);
        if (tx == 0) g_rowsum[bh][it*64 + ty*4 + ii] = v;
    }
}

// ==============================================================================
// attn@v + row normalize + depthwise conv local branch -> g_y[b*S+s][h*64+d]
// ==============================================================================
__global__ __launch_bounds__(256) void attnv_kern(const float* __restrict__ dwc_w,
                                                  const float* __restrict__ dwc_b)
{
    __shared__ float kt[32][68];
    __shared__ float vs[32][64];

    const int tid = threadIdx.x;
    const int tx  = tid & 15;
    const int ty  = tid >> 4;
    const int it  = blockIdx.x;
    const int bh  = blockIdx.y;
    const int bb  = bh >> 4;
    const int h   = bh & 15;

    const float* Kr = &g_kern[bh][it*64][0];
    const float* V  = &g_qkv[2][bh][0][0];

    float acc[4][4];
#pragma unroll
    for (int i = 0; i < 4; i++)
#pragma unroll
        for (int j = 0; j < 4; j++) acc[i][j] = 0.f;

    for (int jt = 0; jt < 32; jt++) {
#pragma unroll
        for (int r = 0; r < 2; r++) {
            int idx = r*1024 + tid*4;
            int i  = idx >> 5, jc = idx & 31;
            float4 kv4 = *(const float4*)(Kr + (size_t)i*1024 + jt*32 + jc);
            kt[jc+0][i] = kv4.x; kt[jc+1][i] = kv4.y;
            kt[jc+2][i] = kv4.z; kt[jc+3][i] = kv4.w;
            int j = idx >> 6, d = idx & 63;
            float4 vv = *(const float4*)(V + (jt*32 + j)*64 + d);
            *(float4*)&vs[j][d] = vv;
        }
        __syncthreads();
#pragma unroll
        for (int kk = 0; kk < 32; kk++) {
            float4 av = *(const float4*)&kt[kk][ty*4];
            float4 bv = *(const float4*)&vs[kk][tx*4];
            const float* ap = &av.x;
            const float* bp = &bv.x;
#pragma unroll
            for (int ii = 0; ii < 4; ii++)
#pragma unroll
                for (int dd = 0; dd < 4; dd++)
                    acc[ii][dd] += ap[ii] * bp[dd];
        }
        __syncthreads();
    }

    const int d0 = tx*4;
#pragma unroll
    for (int ii = 0; ii < 4; ii++) {
        int s = it*64 + ty*4 + ii;
        float scale = 1.0f / (g_rowsum[bh][s] + 1e-6f);
        float4 v0 = *(const float4*)(V + s*64 + d0);
        float4 vm = (s > 0)        ? *(const float4*)(V + (s-1)*64 + d0)
                                   : make_float4(0.f,0.f,0.f,0.f);
        float4 vp = (s < SEQ - 1)  ? *(const float4*)(V + (s+1)*64 + d0)
                                   : make_float4(0.f,0.f,0.f,0.f);
        const float* vmp = &vm.x;
        const float* v0p = &v0.x;
        const float* vpp = &vp.x;
#pragma unroll
        for (int dd = 0; dd < 4; dd++) {
            int c = h*64 + d0 + dd;
            float w0 = dwc_w[c*3+0], w1 = dwc_w[c*3+1], w2 = dwc_w[c*3+2];
            float loc = w0*vmp[dd] + w1*v0p[dd] + w2*vpp[dd] + dwc_b[c];
            g_y[bb*SEQ + s][c] = acc[ii][dd]*scale + loc;
        }
    }
}

// ==============================================================================
extern "C" void kernel_launch(void* const* d_in, const int* in_sizes, int n_in,
                              void* d_out, int out_size)
{
    const float* x      = (const float*)d_in[0];
    const float* qkv_w  = (const float*)d_in[1];
    const float* qkv_b  = (const float*)d_in[2];
    const float* proj_w = (const float*)d_in[3];
    const float* proj_b = (const float*)d_in[4];
    const float* dwc_w  = (const float*)d_in[5];
    const float* dwc_b  = (const float*)d_in[6];
    float* out = (float*)d_out;

    // 1) qkv projection (tf32 tensor cores), scatter to q/k/v
    mma_nt<1><<<dim3(24, 16), 256>>>(x, qkv_w, qkv_b, nullptr, 2048, 3072, 1024);
    // 2) Laplacian L1 kernel matrix + row sums
    laplace_kern<<<dim3(16, 32), 256>>>();
    // 3) kern @ v, normalize, + depthwise conv local branch -> g_y
    attnv_kern<<<dim3(16, 32), 256>>>(dwc_w, dwc_b);
    // 4) output projection (tf32 tensor cores) -> d_out
    mma_nt<0><<<dim3(8, 16), 256>>>(nullptr, proj_w, proj_b, out, 2048, 1024, 1024);
}

// round 4
// speedup vs baseline: 1.8332x; 1.1128x over previous
#include <cuda_runtime.h>
#include <cstdint>

#define SEQ 1024
#define DIMC 1024
#define NHEADS 16
#define HDIM 64
#define NBATCH 2
#define NBH (NBATCH*NHEADS)   // 32

typedef unsigned long long ull;

// ---------------- scratch (device globals; no runtime allocation) -------------
__device__ float g_qkv[3][NBH][SEQ][HDIM];   // 24 MB   q/k/v in [bh][s][d]
__device__ float g_rowsum[NBH][SEQ];         // (unused scratch kept small)
__device__ float g_y[NBATCH*SEQ][DIMC];      // 8 MB    pre-projection activations

// ---------------- small helpers -----------------------------------------------
__device__ __forceinline__ ull f2add(ull a, ull b) {
    ull d;
    asm("add.rn.f32x2 %0, %1, %2;" : "=l"(d) : "l"(a), "l"(b));
    return d;
}
__device__ __forceinline__ ull pk2(float x, float y) {
    return (ull)__float_as_uint(x) | ((ull)__float_as_uint(y) << 32);
}
__device__ __forceinline__ uint32_t smem_u32(const void* p) {
    return (uint32_t)__cvta_generic_to_shared(p);
}
__device__ __forceinline__ void cp16(uint32_t s, const void* g) {
    asm volatile("cp.async.cg.shared.global [%0], [%1], 16;\n" :: "r"(s), "l"(g));
}
__device__ __forceinline__ uint32_t f2tf32(float f) {
    uint32_t r; asm("cvt.rna.tf32.f32 %0, %1;" : "=r"(r) : "f"(f)); return r;
}
__device__ __forceinline__ void mma_tf32(float c[4],
        uint32_t a0, uint32_t a1, uint32_t a2, uint32_t a3,
        uint32_t b0, uint32_t b1) {
    asm volatile(
        "mma.sync.aligned.m16n8k8.row.col.f32.tf32.tf32.f32 "
        "{%0,%1,%2,%3}, {%4,%5,%6,%7}, {%8,%9}, {%0,%1,%2,%3};"
        : "+f"(c[0]), "+f"(c[1]), "+f"(c[2]), "+f"(c[3])
        : "r"(a0), "r"(a1), "r"(a2), "r"(a3), "r"(b0), "r"(b1));
}

// ==============================================================================
// Tensor-core tf32 GEMM (NT): C[m,n] = sum_k A[m,k]*B[n,k] + bias[n]
// BM=BN=128, BK=16, 256 threads (8 warps, each 32x64), 3-stage cp.async.
// MODE 0: A = g_y, row-major store (output projection)
// MODE 1: A = x, scatter into g_qkv with (t,h,d) decode (qkv projection)
// ==============================================================================
#define GEMM_SMEM (3*2*128*20*4)   // 61440 bytes

template<int MODE>
__global__ __launch_bounds__(256, 2) void mma_nt(
    const float* __restrict__ A, const float* __restrict__ B,
    const float* __restrict__ bias, float* __restrict__ C,
    int M, int N, int K)
{
    constexpr int BK  = 16;
    constexpr int PAD = 20;
    extern __shared__ float smg[];
    float (*As)[128][PAD] = (float(*)[128][PAD])smg;
    float (*Bs)[128][PAD] = (float(*)[128][PAD])(smg + 3*128*PAD);

    const int tid  = threadIdx.x;
    const int warp = tid >> 5;
    const int lane = tid & 31;
    const int gr   = lane >> 2;
    const int tg   = lane & 3;
    const int wm   = (warp & 3) * 32;
    const int wn   = (warp >> 2) * 64;
    const int mb   = blockIdx.y * 128;
    const int nb   = blockIdx.x * 128;

    const float* Ap = (MODE == 0) ? &g_y[0][0] : A;

    const int lrow = tid >> 2;
    const int lcol = (tid & 3) * 4;
    const float* aG = Ap + (size_t)(mb + lrow) * K + lcol;
    const float* bG = B  + (size_t)(nb + lrow) * K + lcol;

    float acc[2][8][4];
#pragma unroll
    for (int i = 0; i < 2; i++)
#pragma unroll
        for (int j = 0; j < 8; j++)
#pragma unroll
            for (int r = 0; r < 4; r++) acc[i][j][r] = 0.f;

    auto load_tiles = [&](int st, int k0) {
        cp16(smem_u32(&As[st][lrow     ][lcol]), aG + k0);
        cp16(smem_u32(&As[st][lrow + 64][lcol]), aG + (size_t)64 * K + k0);
        cp16(smem_u32(&Bs[st][lrow     ][lcol]), bG + k0);
        cp16(smem_u32(&Bs[st][lrow + 64][lcol]), bG + (size_t)64 * K + k0);
        asm volatile("cp.async.commit_group;\n");
    };

    const int nK = K / BK;
    load_tiles(0, 0);
    load_tiles(1, BK);

    for (int kt = 0; kt < nK; kt++) {
        asm volatile("cp.async.wait_group 1;\n");
        __syncthreads();
        if (kt + 2 < nK) {
            int st = (kt + 2) % 3;
            load_tiles(st, (kt + 2) * BK);
        }
        const int buf = kt % 3;

#pragma unroll
        for (int ks = 0; ks < 2; ks++) {
            const int k0 = ks * 8;
            uint32_t af[2][4];
#pragma unroll
            for (int i = 0; i < 2; i++) {
                const int r = wm + i * 16;
                af[i][0] = f2tf32(As[buf][r + gr    ][k0 + tg    ]);
                af[i][1] = f2tf32(As[buf][r + gr + 8][k0 + tg    ]);
                af[i][2] = f2tf32(As[buf][r + gr    ][k0 + tg + 4]);
                af[i][3] = f2tf32(As[buf][r + gr + 8][k0 + tg + 4]);
            }
#pragma unroll
            for (int j = 0; j < 8; j++) {
                const int n = wn + j * 8;
                uint32_t b0 = f2tf32(Bs[buf][n + gr][k0 + tg    ]);
                uint32_t b1 = f2tf32(Bs[buf][n + gr][k0 + tg + 4]);
#pragma unroll
                for (int i = 0; i < 2; i++)
                    mma_tf32(acc[i][j], af[i][0], af[i][1], af[i][2], af[i][3],
                             b0, b1);
            }
        }
    }

#pragma unroll
    for (int i = 0; i < 2; i++) {
#pragma unroll
        for (int j = 0; j < 8; j++) {
            const int r0 = mb + wm + i * 16 + gr;
            const int c0 = nb + wn + j * 8 + 2 * tg;
            const float bia0 = bias[c0], bia1 = bias[c0 + 1];
            if (MODE == 1) {
#pragma unroll
                for (int e = 0; e < 4; e++) {
                    const int m = r0 + (e >> 1) * 8;
                    const int n = c0 + (e & 1);
                    const float v = acc[i][j][e] + ((e & 1) ? bia1 : bia0);
                    const int tsel = n >> 10, rem = n & 1023;
                    const int h = rem >> 6, d = rem & 63;
                    const int bb = m >> 10, s = m & 1023;
                    g_qkv[tsel][bb * NHEADS + h][s][d] = v;
                }
            } else {
                float2 lo = make_float2(acc[i][j][0] + bia0, acc[i][j][1] + bia1);
                float2 hi = make_float2(acc[i][j][2] + bia0, acc[i][j][3] + bia1);
                *(float2*)&C[(size_t)r0 * N + c0]        = lo;
                *(float2*)&C[(size_t)(r0 + 8) * N + c0]  = hi;
            }
        }
    }
}

// ==============================================================================
// FUSED: Laplacian kernel tile + (kern @ v) via split-tf32 mma + rownorm + dwc.
// Grid (16 i-tiles, 32 bh), 256 threads / 8 warps.
// Per jt (64-j chunk): load K (packed, negated) + V (tf32 hi/lo split);
//   dist phase (f32x2 add + AND) -> kern tile kh/kl in smem + rowsum;
//   mma phase: acc += kh*vh + kh*vl + kl*vh (fp32-grade accuracy).
// Epilogue: acc/rowsum + depthwise conv local branch -> g_y.
// smem (dynamic): qs 16K | ks 16K | kh 17K | kl 17K | vh 18K | vl 18K | rsum
// ==============================================================================
#define LAPAV_SMEM 104704

__global__ __launch_bounds__(256, 2) void lap_av(const float* __restrict__ dwc_w,
                                                 const float* __restrict__ dwc_b)
{
    extern __shared__ char smraw[];
    ull   (*qs)[64] = (ull(*)[64])(smraw);            // [d2][i]   16384 B
    ull   (*ks)[64] = (ull(*)[64])(smraw + 16384);    // [d2][j]   16384 B
    float (*kh)[68] = (float(*)[68])(smraw + 32768);  // [i][j]    17408 B
    float (*kl)[68] = (float(*)[68])(smraw + 50176);  //           17408 B
    float (*vh)[72] = (float(*)[72])(smraw + 67584);  // [j][d]    18432 B
    float (*vl)[72] = (float(*)[72])(smraw + 86016);  //           18432 B
    float* rsum     = (float*)(smraw + 104448);       // [64]

    const int tid  = threadIdx.x;
    const int tx   = tid & 15;
    const int ty   = tid >> 4;
    const int warp = tid >> 5;
    const int lane = tid & 31;
    const int gr   = lane >> 2;
    const int tg   = lane & 3;
    const int wm   = (warp & 3) * 16;     // 4 warps in M (i)
    const int wn   = (warp >> 2) * 32;    // 2 warps in N (d)
    const int it   = blockIdx.x;          // 0..15
    const int bh   = blockIdx.y;          // 0..31
    const int bb   = bh >> 4;
    const int h    = bh & 15;

    const float* Q  = &g_qkv[0][bh][it*64][0];
    const float* Kp = &g_qkv[1][bh][0][0];
    const float* V  = &g_qkv[2][bh][0][0];

    // load Q tile packed [d2][i]
#pragma unroll
    for (int r = 0; r < 4; r++) {
        int idx = r*1024 + tid*4;
        int i = idx >> 6, d = idx & 63;
        float4 v = *(const float4*)(Q + i*64 + d);
        qs[(d>>1)    ][i] = pk2(v.x, v.y);
        qs[(d>>1) + 1][i] = pk2(v.z, v.w);
    }

    float rs[4]  = {0.f, 0.f, 0.f, 0.f};
    float acc[4][4];
#pragma unroll
    for (int n = 0; n < 4; n++)
#pragma unroll
        for (int r = 0; r < 4; r++) acc[n][r] = 0.f;

    for (int jt = 0; jt < 16; jt++) {
        // ---- load K chunk (packed negated) + V chunk (tf32 split) ----
#pragma unroll
        for (int r = 0; r < 4; r++) {
            int idx = r*1024 + tid*4;
            int j = idx >> 6, d = idx & 63;
            float4 kv = *(const float4*)(Kp + (jt*64 + j)*64 + d);
            ks[(d>>1)    ][j] = pk2(-kv.x, -kv.y);
            ks[(d>>1) + 1][j] = pk2(-kv.z, -kv.w);
            float4 vv = *(const float4*)(V + (jt*64 + j)*64 + d);
            float4 hv, lv;
            {
                float* hp = &hv.x; float* lp = &lv.x;
                const float* sp = &vv.x;
#pragma unroll
                for (int c = 0; c < 4; c++) {
                    uint32_t hb = f2tf32(sp[c]);
                    float hf = __uint_as_float(hb);
                    hp[c] = hf;
                    lp[c] = __uint_as_float(f2tf32(sp[c] - hf));
                }
            }
            *(float4*)&vh[j][d] = hv;
            *(float4*)&vl[j][d] = lv;
        }
        __syncthreads();   // (A) ks/vh/vl ready

        // ---- dist phase: kern 64x64 tile -> kh/kl, rowsum ----
        ull a2[4][4];
#pragma unroll
        for (int ii = 0; ii < 4; ii++)
#pragma unroll
            for (int jj = 0; jj < 4; jj++) a2[ii][jj] = 0ull;

#pragma unroll
        for (int d2 = 0; d2 < 32; d2++) {
            ulonglong2 qa = *(const ulonglong2*)&qs[d2][ty*4];
            ulonglong2 qb = *(const ulonglong2*)&qs[d2][ty*4 + 2];
            ulonglong2 ka = *(const ulonglong2*)&ks[d2][tx*4];
            ulonglong2 kb = *(const ulonglong2*)&ks[d2][tx*4 + 2];
            ull q2[4] = {qa.x, qa.y, qb.x, qb.y};
            ull k2[4] = {ka.x, ka.y, kb.x, kb.y};
#pragma unroll
            for (int ii = 0; ii < 4; ii++)
#pragma unroll
                for (int jj = 0; jj < 4; jj++) {
                    ull t = f2add(q2[ii], k2[jj]) & 0x7FFFFFFF7FFFFFFFull;
                    a2[ii][jj] = f2add(a2[ii][jj], t);
                }
        }

#pragma unroll
        for (int ii = 0; ii < 4; ii++) {
            float khv[4], klv[4];
#pragma unroll
            for (int jj = 0; jj < 4; jj++) {
                ull v = a2[ii][jj];
                float dist = __uint_as_float((unsigned)v)
                           + __uint_as_float((unsigned)(v >> 32));
                float kv = __expf(-0.0625f * dist);
                rs[ii] += kv;
                uint32_t hb = f2tf32(kv);
                float hf = __uint_as_float(hb);
                khv[jj] = hf;
                klv[jj] = __uint_as_float(f2tf32(kv - hf));
            }
            *(float4*)&kh[ty*4 + ii][tx*4] = *(float4*)khv;
            *(float4*)&kl[ty*4 + ii][tx*4] = *(float4*)klv;
        }
        __syncthreads();   // (B) kern tile ready

        // ---- mma phase: acc += kern_tile @ V_chunk (split tf32) ----
#pragma unroll
        for (int k8 = 0; k8 < 8; k8++) {
            const int k0 = k8 * 8;
            uint32_t ah[4], al[4];
            ah[0] = __float_as_uint(kh[wm + gr    ][k0 + tg    ]);
            ah[1] = __float_as_uint(kh[wm + gr + 8][k0 + tg    ]);
            ah[2] = __float_as_uint(kh[wm + gr    ][k0 + tg + 4]);
            ah[3] = __float_as_uint(kh[wm + gr + 8][k0 + tg + 4]);
            al[0] = __float_as_uint(kl[wm + gr    ][k0 + tg    ]);
            al[1] = __float_as_uint(kl[wm + gr + 8][k0 + tg    ]);
            al[2] = __float_as_uint(kl[wm + gr    ][k0 + tg + 4]);
            al[3] = __float_as_uint(kl[wm + gr + 8][k0 + tg + 4]);
#pragma unroll
            for (int n = 0; n < 4; n++) {
                const int n0 = wn + n * 8;
                uint32_t bh0 = __float_as_uint(vh[k0 + tg    ][n0 + gr]);
                uint32_t bh1 = __float_as_uint(vh[k0 + tg + 4][n0 + gr]);
                uint32_t bl0 = __float_as_uint(vl[k0 + tg    ][n0 + gr]);
                uint32_t bl1 = __float_as_uint(vl[k0 + tg + 4][n0 + gr]);
                mma_tf32(acc[n], ah[0], ah[1], ah[2], ah[3], bh0, bh1);
                mma_tf32(acc[n], ah[0], ah[1], ah[2], ah[3], bl0, bl1);
                mma_tf32(acc[n], al[0], al[1], al[2], al[3], bh0, bh1);
            }
        }
        __syncthreads();   // (C) mma done before next chunk overwrites smem
    }

    // ---- rowsum reduce across tx lanes ----
#pragma unroll
    for (int ii = 0; ii < 4; ii++) {
        float v = rs[ii];
        v += __shfl_xor_sync(0xffffffffu, v, 1);
        v += __shfl_xor_sync(0xffffffffu, v, 2);
        v += __shfl_xor_sync(0xffffffffu, v, 4);
        v += __shfl_xor_sync(0xffffffffu, v, 8);
        if (tx == 0) rsum[ty*4 + ii] = v;
    }
    __syncthreads();

    // ---- epilogue: normalize + depthwise conv + store g_y ----
#pragma unroll
    for (int n = 0; n < 4; n++) {
        const int dl = wn + n*8 + 2*tg;
        const int c  = h*64 + dl;
        const float w0a = dwc_w[c*3+0],     w1a = dwc_w[c*3+1];
        const float w2a = dwc_w[c*3+2],     b0a = dwc_b[c];
        const float w0b = dwc_w[(c+1)*3+0], w1b = dwc_w[(c+1)*3+1];
        const float w2b = dwc_w[(c+1)*3+2], b1b = dwc_b[c+1];
#pragma unroll
        for (int half = 0; half < 2; half++) {
            const int il = wm + gr + half*8;
            const int s  = it*64 + il;
            const float sc = 1.0f / (rsum[il] + 1e-6f);
            float o0 = acc[n][half*2 + 0] * sc;
            float o1 = acc[n][half*2 + 1] * sc;
            float2 v0 = *(const float2*)&V[s*64 + dl];
            float2 vm = (s > 0)       ? *(const float2*)&V[(s-1)*64 + dl]
                                      : make_float2(0.f, 0.f);
            float2 vp = (s < SEQ - 1) ? *(const float2*)&V[(s+1)*64 + dl]
                                      : make_float2(0.f, 0.f);
            o0 += w0a*vm.x + w1a*v0.x + w2a*vp.x + b0a;
            o1 += w0b*vm.y + w1b*v0.y + w2b*vp.y + b1b;
            *(float2*)&g_y[bb*SEQ + s][c] = make_float2(o0, o1);
        }
    }
}

// ==============================================================================
extern "C" void kernel_launch(void* const* d_in, const int* in_sizes, int n_in,
                              void* d_out, int out_size)
{
    const float* x      = (const float*)d_in[0];
    const float* qkv_w  = (const float*)d_in[1];
    const float* qkv_b  = (const float*)d_in[2];
    const float* proj_w = (const float*)d_in[3];
    const float* proj_b = (const float*)d_in[4];
    const float* dwc_w  = (const float*)d_in[5];
    const float* dwc_b  = (const float*)d_in[6];
    float* out = (float*)d_out;

    cudaFuncSetAttribute(mma_nt<1>, cudaFuncAttributeMaxDynamicSharedMemorySize, GEMM_SMEM);
    cudaFuncSetAttribute(mma_nt<0>, cudaFuncAttributeMaxDynamicSharedMemorySize, GEMM_SMEM);
    cudaFuncSetAttribute(lap_av,    cudaFuncAttributeMaxDynamicSharedMemorySize, LAPAV_SMEM);

    // 1) qkv projection (tf32 tensor cores, 3-stage pipeline), scatter to q/k/v
    mma_nt<1><<<dim3(24, 16), 256, GEMM_SMEM>>>(x, qkv_w, qkv_b, nullptr, 2048, 3072, 1024);
    // 2) fused Laplacian kernel + attn@v (split-tf32 mma) + rownorm + dwc -> g_y
    lap_av<<<dim3(16, 32), 256, LAPAV_SMEM>>>(dwc_w, dwc_b);
    // 3) output projection (tf32 tensor cores) -> d_out
    mma_nt<0><<<dim3(8, 16), 256, GEMM_SMEM>>>(nullptr, proj_w, proj_b, out, 2048, 1024, 1024);
}

// round 5
// speedup vs baseline: 2.0568x; 1.1219x over previous
#include <cuda_runtime.h>
#include <cuda_fp16.h>
#include <cstdint>

#define SEQ 1024
#define DIMC 1024
#define NHEADS 16
#define HDIM 64
#define NBATCH 2
#define NBH (NBATCH*NHEADS)   // 32

typedef unsigned long long ull;

// ---------------- scratch (device globals; no runtime allocation) -------------
__device__ float  g_qkv[3][NBH][SEQ][HDIM];    // 24 MB  q/k/v [bh][s][d]
__device__ __half g_kern_h[NBH][SEQ][SEQ];     // 67 MB  fp16 kernel matrix
__device__ float  g_rowsum[NBH][SEQ];          // row sums (fp32)
__device__ float  g_y[NBATCH*SEQ][DIMC];       // 8 MB   pre-projection (tf32-rounded)
__device__ float  g_xr[2048*1024];             // tf32-rounded x
__device__ float  g_wqr[3072*1024];            // tf32-rounded qkv_w
__device__ float  g_wpr[1024*1024];            // tf32-rounded proj_w

// ---------------- helpers ------------------------------------------------------
__device__ __forceinline__ ull f2add(ull a, ull b) {
    ull d; asm("add.rn.f32x2 %0, %1, %2;" : "=l"(d) : "l"(a), "l"(b)); return d;
}
__device__ __forceinline__ ull pk2(float x, float y) {
    return (ull)__float_as_uint(x) | ((ull)__float_as_uint(y) << 32);
}
__device__ __forceinline__ uint32_t smem_u32(const void* p) {
    return (uint32_t)__cvta_generic_to_shared(p);
}
__device__ __forceinline__ void cp16(uint32_t s, const void* g) {
    asm volatile("cp.async.cg.shared.global [%0], [%1], 16;\n" :: "r"(s), "l"(g));
}
__device__ __forceinline__ uint32_t f2tf32(float f) {
    uint32_t r; asm("cvt.rna.tf32.f32 %0, %1;" : "=r"(r) : "f"(f)); return r;
}
__device__ __forceinline__ void mma_tf32(float c[4],
        uint32_t a0, uint32_t a1, uint32_t a2, uint32_t a3,
        uint32_t b0, uint32_t b1) {
    asm volatile(
        "mma.sync.aligned.m16n8k8.row.col.f32.tf32.tf32.f32 "
        "{%0,%1,%2,%3}, {%4,%5,%6,%7}, {%8,%9}, {%0,%1,%2,%3};"
        : "+f"(c[0]), "+f"(c[1]), "+f"(c[2]), "+f"(c[3])
        : "r"(a0), "r"(a1), "r"(a2), "r"(a3), "r"(b0), "r"(b1));
}
__device__ __forceinline__ void mma_f16(float c[4],
        uint32_t a0, uint32_t a1, uint32_t a2, uint32_t a3,
        uint32_t b0, uint32_t b1) {
    asm volatile(
        "mma.sync.aligned.m16n8k16.row.col.f32.f16.f16.f32 "
        "{%0,%1,%2,%3}, {%4,%5,%6,%7}, {%8,%9}, {%0,%1,%2,%3};"
        : "+f"(c[0]), "+f"(c[1]), "+f"(c[2]), "+f"(c[3])
        : "r"(a0), "r"(a1), "r"(a2), "r"(a3), "r"(b0), "r"(b1));
}
__device__ __forceinline__ void ldsm4(uint32_t& r0, uint32_t& r1,
                                      uint32_t& r2, uint32_t& r3, uint32_t a) {
    asm volatile("ldmatrix.sync.aligned.m8n8.x4.shared.b16 {%0,%1,%2,%3}, [%4];"
                 : "=r"(r0), "=r"(r1), "=r"(r2), "=r"(r3) : "r"(a));
}
__device__ __forceinline__ void ldsm2t(uint32_t& r0, uint32_t& r1, uint32_t a) {
    asm volatile("ldmatrix.sync.aligned.m8n8.x2.trans.shared.b16 {%0,%1}, [%2];"
                 : "=r"(r0), "=r"(r1) : "r"(a));
}
__device__ __forceinline__ uint32_t h2u(__half2 h) { return *(uint32_t*)&h; }

// ==============================================================================
// Prepass: round x / qkv_w / proj_w to tf32 into scratch copies.
// ==============================================================================
__global__ __launch_bounds__(256) void tf32_prep(const float* __restrict__ x,
                                                 const float* __restrict__ wq,
                                                 const float* __restrict__ wp)
{
    const float4* src; float4* dst; int n4;
    if (blockIdx.y == 0)      { src = (const float4*)x;  dst = (float4*)g_xr;  n4 = 524288; }
    else if (blockIdx.y == 1) { src = (const float4*)wq; dst = (float4*)g_wqr; n4 = 786432; }
    else                      { src = (const float4*)wp; dst = (float4*)g_wpr; n4 = 262144; }
    int i = blockIdx.x * 256 + threadIdx.x;
    if (i < n4) {
        float4 v = src[i];
        v.x = __uint_as_float(f2tf32(v.x));
        v.y = __uint_as_float(f2tf32(v.y));
        v.z = __uint_as_float(f2tf32(v.z));
        v.w = __uint_as_float(f2tf32(v.w));
        dst[i] = v;
    }
}

// ==============================================================================
// Tensor-core tf32 GEMM (NT): C[m,n] = sum_k A[m,k]*B[n,k] + bias[n]
// Inputs pre-rounded to tf32 -> no CVT in inner loop.
// MODE 0: A=g_y, B=g_wpr, row-major store. MODE 1: A=g_xr, B=g_wqr, qkv scatter.
// ==============================================================================
#define GEMM_SMEM (3*2*128*20*4)   // 61440 bytes

template<int MODE>
__global__ __launch_bounds__(256, 2) void mma_nt(
    const float* __restrict__ bias, float* __restrict__ C, int N, int K)
{
    constexpr int BK  = 16;
    constexpr int PAD = 20;
    extern __shared__ float smg[];
    float (*As)[128][PAD] = (float(*)[128][PAD])smg;
    float (*Bs)[128][PAD] = (float(*)[128][PAD])(smg + 3*128*PAD);

    const int tid  = threadIdx.x;
    const int warp = tid >> 5;
    const int lane = tid & 31;
    const int gr   = lane >> 2;
    const int tg   = lane & 3;
    const int wm   = (warp & 3) * 32;
    const int wn   = (warp >> 2) * 64;
    const int mb   = blockIdx.y * 128;
    const int nb   = blockIdx.x * 128;

    const float* Ap = (MODE == 0) ? &g_y[0][0] : g_xr;
    const float* Bp = (MODE == 0) ? g_wpr      : g_wqr;

    const int lrow = tid >> 2;
    const int lcol = (tid & 3) * 4;
    const float* aG = Ap + (size_t)(mb + lrow) * K + lcol;
    const float* bG = Bp + (size_t)(nb + lrow) * K + lcol;

    float acc[2][8][4];
#pragma unroll
    for (int i = 0; i < 2; i++)
#pragma unroll
        for (int j = 0; j < 8; j++)
#pragma unroll
            for (int r = 0; r < 4; r++) acc[i][j][r] = 0.f;

    auto load_tiles = [&](int st, int k0) {
        cp16(smem_u32(&As[st][lrow     ][lcol]), aG + k0);
        cp16(smem_u32(&As[st][lrow + 64][lcol]), aG + (size_t)64 * K + k0);
        cp16(smem_u32(&Bs[st][lrow     ][lcol]), bG + k0);
        cp16(smem_u32(&Bs[st][lrow + 64][lcol]), bG + (size_t)64 * K + k0);
        asm volatile("cp.async.commit_group;\n");
    };

    const int nK = K / BK;
    load_tiles(0, 0);
    load_tiles(1, BK);

    for (int kt = 0; kt < nK; kt++) {
        asm volatile("cp.async.wait_group 1;\n");
        __syncthreads();
        if (kt + 2 < nK) load_tiles((kt + 2) % 3, (kt + 2) * BK);
        const int buf = kt % 3;

#pragma unroll
        for (int ks = 0; ks < 2; ks++) {
            const int k0 = ks * 8;
            uint32_t af[2][4];
#pragma unroll
            for (int i = 0; i < 2; i++) {
                const int r = wm + i * 16;
                af[i][0] = __float_as_uint(As[buf][r + gr    ][k0 + tg    ]);
                af[i][1] = __float_as_uint(As[buf][r + gr + 8][k0 + tg    ]);
                af[i][2] = __float_as_uint(As[buf][r + gr    ][k0 + tg + 4]);
                af[i][3] = __float_as_uint(As[buf][r + gr + 8][k0 + tg + 4]);
            }
#pragma unroll
            for (int j = 0; j < 8; j++) {
                const int n = wn + j * 8;
                uint32_t b0 = __float_as_uint(Bs[buf][n + gr][k0 + tg    ]);
                uint32_t b1 = __float_as_uint(Bs[buf][n + gr][k0 + tg + 4]);
#pragma unroll
                for (int i = 0; i < 2; i++)
                    mma_tf32(acc[i][j], af[i][0], af[i][1], af[i][2], af[i][3],
                             b0, b1);
            }
        }
    }

#pragma unroll
    for (int i = 0; i < 2; i++) {
#pragma unroll
        for (int j = 0; j < 8; j++) {
            const int r0 = mb + wm + i * 16 + gr;
            const int c0 = nb + wn + j * 8 + 2 * tg;
            const float bia0 = bias[c0], bia1 = bias[c0 + 1];
            if (MODE == 1) {
#pragma unroll
                for (int e = 0; e < 4; e++) {
                    const int m = r0 + (e >> 1) * 8;
                    const int n = c0 + (e & 1);
                    const float v = acc[i][j][e] + ((e & 1) ? bia1 : bia0);
                    const int tsel = n >> 10, rem = n & 1023;
                    const int h = rem >> 6, d = rem & 63;
                    const int bb = m >> 10, s = m & 1023;
                    g_qkv[tsel][bb * NHEADS + h][s][d] = v;
                }
            } else {
                float2 lo = make_float2(acc[i][j][0] + bia0, acc[i][j][1] + bia1);
                float2 hi = make_float2(acc[i][j][2] + bia0, acc[i][j][3] + bia1);
                *(float2*)&C[(size_t)r0 * N + c0]        = lo;
                *(float2*)&C[(size_t)(r0 + 8) * N + c0]  = hi;
            }
        }
    }
}

// ==============================================================================
// Laplacian kernel (standalone, proven issue-bound): kern fp16 + fp32 rowsum.
// Grid (16 i-tiles, 32 bh), 256 threads, 4x4 microtile, packed f32x2 L1 distance.
// ==============================================================================
__global__ __launch_bounds__(256) void laplace_kern()
{
    __shared__ ull qs[32][64];   // [d/2][i]
    __shared__ ull ks[32][64];   // [d/2][j]  (stores -k)

    const int tid = threadIdx.x;
    const int tx  = tid & 15;
    const int ty  = tid >> 4;
    const int it  = blockIdx.x;
    const int bh  = blockIdx.y;

    const float* Q  = &g_qkv[0][bh][it*64][0];
    const float* Kp = &g_qkv[1][bh][0][0];

#pragma unroll
    for (int r = 0; r < 4; r++) {
        int idx = r*1024 + tid*4;
        int i = idx >> 6, d = idx & 63;
        float4 v = *(const float4*)(Q + i*64 + d);
        qs[(d>>1)    ][i] = pk2(v.x, v.y);
        qs[(d>>1) + 1][i] = pk2(v.z, v.w);
    }

    float rs[4] = {0.f, 0.f, 0.f, 0.f};
    char* kout = (char*)&g_kern_h[bh][it*64][0];

    for (int jt = 0; jt < 16; jt++) {
#pragma unroll
        for (int r = 0; r < 4; r++) {
            int idx = r*1024 + tid*4;
            int j = idx >> 6, d = idx & 63;
            float4 v = *(const float4*)(Kp + (jt*64 + j)*64 + d);
            ks[(d>>1)    ][j] = pk2(-v.x, -v.y);
            ks[(d>>1) + 1][j] = pk2(-v.z, -v.w);
        }
        __syncthreads();

        ull a2[4][4];
#pragma unroll
        for (int ii = 0; ii < 4; ii++)
#pragma unroll
            for (int jj = 0; jj < 4; jj++) a2[ii][jj] = 0ull;

#pragma unroll
        for (int d2 = 0; d2 < 32; d2++) {
            ulonglong2 qa = *(const ulonglong2*)&qs[d2][ty*4];
            ulonglong2 qb = *(const ulonglong2*)&qs[d2][ty*4 + 2];
            ulonglong2 ka = *(const ulonglong2*)&ks[d2][tx*4];
            ulonglong2 kb = *(const ulonglong2*)&ks[d2][tx*4 + 2];
            ull q2[4] = {qa.x, qa.y, qb.x, qb.y};
            ull k2[4] = {ka.x, ka.y, kb.x, kb.y};
#pragma unroll
            for (int ii = 0; ii < 4; ii++)
#pragma unroll
                for (int jj = 0; jj < 4; jj++) {
                    ull t = f2add(q2[ii], k2[jj]) & 0x7FFFFFFF7FFFFFFFull;
                    a2[ii][jj] = f2add(a2[ii][jj], t);
                }
        }

#pragma unroll
        for (int ii = 0; ii < 4; ii++) {
            float op[4];
#pragma unroll
            for (int jj = 0; jj < 4; jj++) {
                ull v = a2[ii][jj];
                float dist = __uint_as_float((unsigned)v)
                           + __uint_as_float((unsigned)(v >> 32));
                float kv = __expf(-0.0625f * dist);
                op[jj] = kv;
                rs[ii] += kv;
            }
            __half2 p01 = __floats2half2_rn(op[0], op[1]);
            __half2 p23 = __floats2half2_rn(op[2], op[3]);
            *(uint2*)(kout + ((size_t)(ty*4 + ii)*1024 + jt*64 + tx*4)*2)
                = make_uint2(h2u(p01), h2u(p23));
        }
        __syncthreads();
    }

#pragma unroll
    for (int ii = 0; ii < 4; ii++) {
        float v = rs[ii];
        v += __shfl_xor_sync(0xffffffffu, v, 1);
        v += __shfl_xor_sync(0xffffffffu, v, 2);
        v += __shfl_xor_sync(0xffffffffu, v, 4);
        v += __shfl_xor_sync(0xffffffffu, v, 8);
        if (tx == 0) g_rowsum[bh][it*64 + ty*4 + ii] = v;
    }
}

// ==============================================================================
// attnv_tc: global = (kern_fp16 @ v) via m16n8k16 HMMA; v in fp16 hi/lo (2 mmas).
// + row normalize + depthwise conv + store g_y (tf32-rounded).
// Grid (8 i-tiles of 128, 32 bh). 256 threads = 8 warps, each m16 x n64.
// Double-buffered: kern tile via cp.async, v chunk via LDG->cvt->STS.
// smem/stage: A 128x72h (18432) | vh 64x72h (9216) | vl (9216) = 36864; x2 stages.
// ==============================================================================
#define AV_STAGE 36864
#define AV_SMEM  (2*AV_STAGE)

__global__ __launch_bounds__(256, 2) void attnv_tc(const float* __restrict__ dwc_w,
                                                   const float* __restrict__ dwc_b)
{
    extern __shared__ char sm[];
    const int tid  = threadIdx.x;
    const int warp = tid >> 5;
    const int lane = tid & 31;
    const int gr   = lane >> 2;
    const int tg   = lane & 3;
    const int it   = blockIdx.x;
    const int bh   = blockIdx.y;
    const int bb   = bh >> 4;
    const int h    = bh & 15;

    const __half* Kh = &g_kern_h[bh][0][0];
    const float*  V  = &g_qkv[2][bh][0][0];
    const uint32_t smBase = smem_u32(sm);

    float acc[8][4];
#pragma unroll
    for (int n = 0; n < 8; n++)
#pragma unroll
        for (int e = 0; e < 4; e++) acc[n][e] = 0.f;

    // per-thread load coords
    const int arow = tid >> 3, achk = tid & 7;        // kern cp.async
    const int vrow = tid >> 4, vd = (tid & 15) * 4;   // v ldg/sts

    auto issue_kern = [&](int st, int k0) {
        const uint32_t dst = smBase + st * AV_STAGE;
#pragma unroll
        for (int q = 0; q < 4; q++) {
            int r = arow + 32 * q;
            cp16(dst + r * 144 + achk * 16,
                 Kh + (size_t)(it * 128 + r) * 1024 + k0 + achk * 8);
        }
        asm volatile("cp.async.commit_group;\n");
    };
    auto ldg_v = [&](int k0, float4* vr) {
#pragma unroll
        for (int q = 0; q < 4; q++)
            vr[q] = *(const float4*)(V + (size_t)(k0 + vrow + 16 * q) * 64 + vd);
    };
    auto sts_v = [&](int st, const float4* vr) {
        char* vhB = sm + st * AV_STAGE + 18432;
        char* vlB = sm + st * AV_STAGE + 27648;
#pragma unroll
        for (int q = 0; q < 4; q++) {
            int r = vrow + 16 * q;
            float4 vv = vr[q];
            __half hx = __float2half_rn(vv.x), hy = __float2half_rn(vv.y);
            __half hz = __float2half_rn(vv.z), hw = __float2half_rn(vv.w);
            __half2 hi0 = __halves2half2(hx, hy), hi1 = __halves2half2(hz, hw);
            __half2 lo0 = __floats2half2_rn(vv.x - __half2float(hx),
                                            vv.y - __half2float(hy));
            __half2 lo1 = __floats2half2_rn(vv.z - __half2float(hz),
                                            vv.w - __half2float(hw));
            *(uint2*)(vhB + r * 144 + vd * 2) = make_uint2(h2u(hi0), h2u(hi1));
            *(uint2*)(vlB + r * 144 + vd * 2) = make_uint2(h2u(lo0), h2u(lo1));
        }
    };

    // fragment addresses (lane-dependent, stage-relative)
    const uint32_t aOff = (uint32_t)((warp * 16 + (lane & 7) + ((lane >> 3) & 1) * 8) * 144
                                     + (lane >> 4) * 16);
    const uint32_t bRow = (uint32_t)((lane & 15) * 144);

    // prologue: stage 0
    issue_kern(0, 0);
    {
        float4 vr[4];
        ldg_v(0, vr);
        sts_v(0, vr);
    }

    for (int kt = 0; kt < 16; kt++) {
        const int cur = kt & 1;
        asm volatile("cp.async.wait_group 0;\n");
        __syncthreads();

        float4 vr[4];
        if (kt < 15) {
            issue_kern(cur ^ 1, (kt + 1) * 64);
            ldg_v((kt + 1) * 64, vr);
        }

        const uint32_t aB  = smBase + cur * AV_STAGE + aOff;
        const uint32_t vhB = smBase + cur * AV_STAGE + 18432 + bRow;
        const uint32_t vlB = smBase + cur * AV_STAGE + 27648 + bRow;
#pragma unroll
        for (int k16 = 0; k16 < 4; k16++) {
            uint32_t a0, a1, a2, a3;
            ldsm4(a0, a1, a2, a3, aB + k16 * 32);
#pragma unroll
            for (int nf = 0; nf < 8; nf++) {
                uint32_t bh0, bh1, bl0, bl1;
                ldsm2t(bh0, bh1, vhB + k16 * 2304 + nf * 16);
                ldsm2t(bl0, bl1, vlB + k16 * 2304 + nf * 16);
                mma_f16(acc[nf], a0, a1, a2, a3, bh0, bh1);
                mma_f16(acc[nf], a0, a1, a2, a3, bl0, bl1);
            }
        }

        if (kt < 15) sts_v(cur ^ 1, vr);
    }

    // ---- epilogue: normalize + depthwise conv + tf32-rounded store to g_y ----
    const int m0 = it * 128 + warp * 16 + gr;
#pragma unroll
    for (int nf = 0; nf < 8; nf++) {
        const int dl = nf * 8 + tg * 2;
        const int c  = h * 64 + dl;
        const float w0a = dwc_w[c*3+0], w1a = dwc_w[c*3+1], w2a = dwc_w[c*3+2];
        const float b0a = dwc_b[c];
        const float w0b = dwc_w[c*3+3], w1b = dwc_w[c*3+4], w2b = dwc_w[c*3+5];
        const float b1b = dwc_b[c+1];
#pragma unroll
        for (int half = 0; half < 2; half++) {
            const int s = m0 + half * 8;
            const float sc = 1.0f / (g_rowsum[bh][s] + 1e-6f);
            float o0 = acc[nf][half*2 + 0] * sc;
            float o1 = acc[nf][half*2 + 1] * sc;
            float2 v0 = *(const float2*)&V[(size_t)s*64 + dl];
            float2 vm = (s > 0)       ? *(const float2*)&V[(size_t)(s-1)*64 + dl]
                                      : make_float2(0.f, 0.f);
            float2 vp = (s < SEQ - 1) ? *(const float2*)&V[(size_t)(s+1)*64 + dl]
                                      : make_float2(0.f, 0.f);
            o0 += w0a*vm.x + w1a*v0.x + w2a*vp.x + b0a;
            o1 += w0b*vm.y + w1b*v0.y + w2b*vp.y + b1b;
            o0 = __uint_as_float(f2tf32(o0));   // pre-round for proj GEMM
            o1 = __uint_as_float(f2tf32(o1));
            *(float2*)&g_y[bb*SEQ + s][c] = make_float2(o0, o1);
        }
    }
}

// ==============================================================================
extern "C" void kernel_launch(void* const* d_in, const int* in_sizes, int n_in,
                              void* d_out, int out_size)
{
    const float* x      = (const float*)d_in[0];
    const float* qkv_w  = (const float*)d_in[1];
    const float* qkv_b  = (const float*)d_in[2];
    const float* proj_w = (const float*)d_in[3];
    const float* proj_b = (const float*)d_in[4];
    const float* dwc_w  = (const float*)d_in[5];
    const float* dwc_b  = (const float*)d_in[6];
    float* out = (float*)d_out;

    cudaFuncSetAttribute(mma_nt<1>, cudaFuncAttributeMaxDynamicSharedMemorySize, GEMM_SMEM);
    cudaFuncSetAttribute(mma_nt<0>, cudaFuncAttributeMaxDynamicSharedMemorySize, GEMM_SMEM);
    cudaFuncSetAttribute(attnv_tc,  cudaFuncAttributeMaxDynamicSharedMemorySize, AV_SMEM);

    // 0) round x / weights to tf32 scratch copies
    tf32_prep<<<dim3(3072, 3), 256>>>(x, qkv_w, proj_w);
    // 1) qkv projection (tf32 HMMA, no inner-loop CVT), scatter to q/k/v
    mma_nt<1><<<dim3(24, 16), 256, GEMM_SMEM>>>(qkv_b, nullptr, 3072, 1024);
    // 2) Laplacian L1 kernel matrix (fp16) + fp32 row sums
    laplace_kern<<<dim3(16, 32), 256>>>();
    // 3) kern_fp16 @ v (fp16 HMMA, v hi/lo) + normalize + dwc -> g_y (tf32)
    attnv_tc<<<dim3(8, 32), 256, AV_SMEM>>>(dwc_w, dwc_b);
    // 4) output projection -> d_out
    mma_nt<0><<<dim3(8, 16), 256, GEMM_SMEM>>>(proj_b, out, 1024, 1024);
}